// round 17
// baseline (speedup 1.0000x reference)
#include <cuda_runtime.h>
#include <cuda_fp16.h>
#include <cstdint>
#include <cstddef>

#define Mdim 256
#define Ndim 1024
#define Bdim 16384
#define Kiter 16
#define Pk 50u

// ---------------------------------------------------------------------------
// Scratch (allocation-free __device__ globals). Batch-major layout.
// ALL GEMM operands persisted as packed half2 hi/lo (same bytes as fp32).
// ---------------------------------------------------------------------------
__device__ uint32_t g_xh2[(size_t)Bdim * Ndim / 2];  // x hi (B, N/2)
__device__ uint32_t g_xl2[(size_t)Bdim * Ndim / 2];  // x lo
__device__ uint32_t g_rh2[(size_t)Bdim * Mdim / 2];  // r hi (B, M/2)
__device__ uint32_t g_rl2[(size_t)Bdim * Mdim / 2];  // r lo
__device__ float    g_c  [(size_t)Bdim * Ndim];      // c (B,N) fp32; head reused as W^T temp
__device__ uint32_t g_phih2[(size_t)Mdim * Ndim / 2];
__device__ uint32_t g_phil2[(size_t)Mdim * Ndim / 2];
__device__ uint32_t g_wth2 [(size_t)Ndim * Mdim / 2];
__device__ uint32_t g_wtl2 [(size_t)Ndim * Mdim / 2];

// ---------------------------------------------------------------------------
// PTX helpers (plain-sm_103-legal: cp.async sm_80+, mma.sync f16 sm_80+)
// ---------------------------------------------------------------------------
__device__ __forceinline__ void cp_async16(uint32_t saddr, const void* gaddr) {
    asm volatile("cp.async.cg.shared.global [%0], [%1], 16;\n"
                 :: "r"(saddr), "l"(gaddr));
}
#define CP_COMMIT() asm volatile("cp.async.commit_group;\n" ::: "memory")
#define CP_WAIT0()  asm volatile("cp.async.wait_group 0;\n" ::: "memory")
#define CP_WAIT1()  asm volatile("cp.async.wait_group 1;\n" ::: "memory")

// fp16 split of a float2 pair: hi = rn(v) packed half2, lo = rn(v - hi).
__device__ __forceinline__ void h2split(float2 v, uint32_t& hi, uint32_t& lo) {
    __half2 h = __floats2half2_rn(v.x, v.y);
    float2 hf = __half22float2(h);
    __half2 l = __floats2half2_rn(v.x - hf.x, v.y - hf.y);
    hi = *reinterpret_cast<uint32_t*>(&h);
    lo = *reinterpret_cast<uint32_t*>(&l);
}

__device__ __forceinline__ float2 h2pair(uint32_t hi, uint32_t lo) {
    float2 h = __half22float2(*reinterpret_cast<__half2*>(&hi));
    float2 l = __half22float2(*reinterpret_cast<__half2*>(&lo));
    return make_float2(h.x + l.x, h.y + l.y);
}

__device__ __forceinline__ void mma_f16(float* d, const uint32_t* a,
                                        const uint32_t* b) {
    asm volatile(
        "mma.sync.aligned.m16n8k16.row.col.f32.f16.f16.f32 "
        "{%0,%1,%2,%3}, {%4,%5,%6,%7}, {%8,%9}, {%0,%1,%2,%3};"
        : "+f"(d[0]), "+f"(d[1]), "+f"(d[2]), "+f"(d[3])
        : "r"(a[0]), "r"(a[1]), "r"(a[2]), "r"(a[3]),
          "r"(b[0]), "r"(b[1]));
}

// ---------------------------------------------------------------------------
// FP16x3 GEMM, ALL operands pre-split packed half2:
//   D = (Ah+Al)(B,Kd) @ (Bh+Bl)(Nrows,Kd)^T   [- Sub if SPLIT_OUT]
// Mainloop: pure LDS.32 + MMA (zero conversions).
// Tile 128(b) x 128(n) x 16(k), 256 threads (2x4 warps), warp tile 64x32.
// SPLIT_OUT=1: subtract Sub, write packed hi/lo (gemm1 -> r).
// SPLIT_OUT=0: write fp32 (gemm2 -> c).
// ROWPAD=12 uint32 (48B rows): 16B-aligned cp.async, conflict-free frags.
// ---------------------------------------------------------------------------
#define KTILE 16
#define ROWPAD 12
#define OPBYTES (128 * ROWPAD * 4)           // 6144 per operand array
#define STAGE_BYTES (4 * OPBYTES)            // 24576 (Ah, Al, Bh, Bl)
#define GEMM_SMEM (2 * STAGE_BYTES)          // 49152

template<int SPLIT_OUT>
__global__ void __launch_bounds__(256)
gemm_tc(const uint32_t* __restrict__ Ah2, const uint32_t* __restrict__ Al2,
        const uint32_t* __restrict__ Bh2, const uint32_t* __restrict__ Bl2,
        float* __restrict__ Df, uint32_t* __restrict__ Dh2,
        uint32_t* __restrict__ Dl2, const float* __restrict__ Sub,
        int Kd, int CStride)
{
    extern __shared__ float sm[];
    const int tid  = threadIdx.x;
    const int wid  = tid >> 5;
    const int lane = tid & 31;
    const int gid  = lane >> 2;
    const int tig  = lane & 3;
    const int wm   = wid >> 2;       // 0..1 -> 64-row strip (batch)
    const int wn   = wid & 3;        // 0..3 -> 32-col strip (n)
    const int b0   = blockIdx.y * 128;
    const int n0   = blockIdx.x * 128;
    const uint32_t smbase = (uint32_t)__cvta_generic_to_shared(sm);
    const int Kh = Kd >> 1;          // packed row stride

    float acc[4][4][4];
#pragma unroll
    for (int i = 0; i < 4; i++)
#pragma unroll
        for (int j = 0; j < 4; j++)
#pragma unroll
            for (int q = 0; q < 4; q++) acc[i][j][q] = 0.0f;

    // Loader: 4 arrays x 128 rows x 2 chunks(16B) = 1024 chunks; 4/thread.
    auto load_stage = [&](int t, int buf) {
        const int kh0 = (t * KTILE) >> 1;
        const uint32_t sb = smbase + buf * STAGE_BYTES;
        int row = tid >> 1;                    // 0..127
        int ch  = tid & 1;                     // 0..1
        uint32_t so = (row * ROWPAD + ch * 4) * 4;
        cp_async16(sb + so,
                   Ah2 + (size_t)(b0 + row) * Kh + kh0 + ch * 4);
        cp_async16(sb + OPBYTES + so,
                   Al2 + (size_t)(b0 + row) * Kh + kh0 + ch * 4);
        cp_async16(sb + 2 * OPBYTES + so,
                   Bh2 + (size_t)(n0 + row) * Kh + kh0 + ch * 4);
        cp_async16(sb + 3 * OPBYTES + so,
                   Bl2 + (size_t)(n0 + row) * Kh + kh0 + ch * 4);
    };

    const int T = Kd / KTILE;
    load_stage(0, 0);
    CP_COMMIT();

    for (int t = 0; t < T; t++) {
        const int buf = t & 1;
        if (t + 1 < T) {
            load_stage(t + 1, buf ^ 1);
            CP_COMMIT();
            CP_WAIT1();
        } else {
            CP_WAIT0();
        }
        __syncthreads();

        const uint32_t* Ah = (const uint32_t*)sm + buf * (STAGE_BYTES / 4);
        const uint32_t* Al = Ah + OPBYTES / 4;
        const uint32_t* Bh = Al + OPBYTES / 4;
        const uint32_t* Bl = Bh + OPBYTES / 4;

        // B fragments: b0 = k pair tig, b1 = k pair tig+4; col gid
        uint32_t bhi[4][2], blo[4][2];
#pragma unroll
        for (int nt = 0; nt < 4; nt++) {
            int n = wn * 32 + nt * 8 + gid;
            bhi[nt][0] = Bh[n * ROWPAD + tig];
            bhi[nt][1] = Bh[n * ROWPAD + tig + 4];
            blo[nt][0] = Bl[n * ROWPAD + tig];
            blo[nt][1] = Bl[n * ROWPAD + tig + 4];
        }
#pragma unroll
        for (int mt = 0; mt < 4; mt++) {
            int m = wm * 64 + mt * 16 + gid;
            uint32_t ahi[4], alo[4];
            ahi[0] = Ah[m * ROWPAD + tig];
            ahi[1] = Ah[(m + 8) * ROWPAD + tig];
            ahi[2] = Ah[m * ROWPAD + tig + 4];
            ahi[3] = Ah[(m + 8) * ROWPAD + tig + 4];
            alo[0] = Al[m * ROWPAD + tig];
            alo[1] = Al[(m + 8) * ROWPAD + tig];
            alo[2] = Al[m * ROWPAD + tig + 4];
            alo[3] = Al[(m + 8) * ROWPAD + tig + 4];
            // term-major: consecutive MMAs touch different accumulators
#pragma unroll
            for (int nt = 0; nt < 4; nt++)
                mma_f16(acc[mt][nt], ahi, bhi[nt]);
#pragma unroll
            for (int nt = 0; nt < 4; nt++)
                mma_f16(acc[mt][nt], ahi, blo[nt]);
#pragma unroll
            for (int nt = 0; nt < 4; nt++)
                mma_f16(acc[mt][nt], alo, bhi[nt]);
        }
        __syncthreads();
    }

    // Epilogue. Fragment: c0:(r,2c) c1:(r,2c+1) c2:(r+8,2c) c3:(r+8,2c+1)
    const int Ch = CStride >> 1;
#pragma unroll
    for (int mt = 0; mt < 4; mt++) {
        int r0 = b0 + wm * 64 + mt * 16 + gid;
#pragma unroll
        for (int nt = 0; nt < 4; nt++) {
            int col = n0 + wn * 32 + nt * 8 + tig * 2;
#pragma unroll
            for (int half = 0; half < 2; half++) {
                int rr = r0 + half * 8;
                float2 v = make_float2(acc[mt][nt][half * 2],
                                       acc[mt][nt][half * 2 + 1]);
                if (SPLIT_OUT) {
                    float2 yv = *(const float2*)(Sub + (size_t)rr * CStride + col);
                    v.x -= yv.x;
                    v.y -= yv.y;
                    uint32_t h, l;
                    h2split(v, h, l);
                    size_t o = (size_t)rr * Ch + (col >> 1);
                    Dh2[o] = h;
                    Dl2[o] = l;
                } else {
                    *(float2*)(Df + (size_t)rr * CStride + col) = v;
                }
            }
        }
    }
}

// ---------------------------------------------------------------------------
// Fused update on (B,N): one warp per batch row.
// x reconstructed from packed hi/lo; v = x - gamma*c; thr = exact Pk-th
// largest |v| (radix select); res = keep ? v : soft(v, theta*g(|x|)).
// LAST=0: write packed half2 split back to xh2/xl2.  LAST=1: fp32 to outp.
// ---------------------------------------------------------------------------
template<int LAST>
__global__ void __launch_bounds__(256)
update_kernel(uint32_t* __restrict__ xh2, uint32_t* __restrict__ xl2,
              const float* __restrict__ c, float* __restrict__ outp,
              const float* __restrict__ gammaArr,
              const float* __restrict__ thetaArr, int it)
{
    __shared__ float    v[8][1024];
    __shared__ unsigned hist[8][256];

    const int tid  = threadIdx.x;
    const int w    = tid >> 5;
    const int lane = tid & 31;
    const size_t base  = ((size_t)blockIdx.x * 8 + w) * Ndim;
    const size_t base2 = base >> 1;
    const float gamma = gammaArr[it];
    const float theta = thetaArr[it];

    float xabs[32];
#pragma unroll
    for (int i = 0; i < 8; i++) {
        int n = i * 128 + lane * 4;         // 4 values = 2 packed uint32
        uint2 xh = *(const uint2*)(xh2 + base2 + (n >> 1));
        uint2 xl = *(const uint2*)(xl2 + base2 + (n >> 1));
        float4 cc = *(const float4*)(c + base + n);
        float2 p0 = h2pair(xh.x, xl.x);
        float2 p1 = h2pair(xh.y, xl.y);
        xabs[i * 4 + 0] = fabsf(p0.x);
        xabs[i * 4 + 1] = fabsf(p0.y);
        xabs[i * 4 + 2] = fabsf(p1.x);
        xabs[i * 4 + 3] = fabsf(p1.y);
        float4 vv;
        vv.x = p0.x - gamma * cc.x;
        vv.y = p0.y - gamma * cc.y;
        vv.z = p1.x - gamma * cc.z;
        vv.w = p1.y - gamma * cc.w;
        *(float4*)(&v[w][n]) = vv;
    }
    __syncwarp();

    unsigned prefix = 0u, mask = 0u, k = Pk;
    unsigned* h = hist[w];
#pragma unroll
    for (int pass = 0; pass < 4; pass++) {
        const int shift = 24 - 8 * pass;
#pragma unroll
        for (int i = lane; i < 256; i += 32) h[i] = 0u;
        __syncwarp();
        for (int n = lane; n < 1024; n += 32) {
            unsigned e = __float_as_uint(v[w][n]) & 0x7FFFFFFFu;
            if ((e & mask) == prefix)
                atomicAdd(&h[(e >> shift) & 0xFFu], 1u);
        }
        __syncwarp();
        unsigned loc[8];
        unsigned s = 0u;
#pragma unroll
        for (int r = 7; r >= 0; r--) { s += h[lane * 8 + r]; loc[r] = s; }
        unsigned inc = s;
#pragma unroll
        for (int off = 1; off < 32; off <<= 1) {
            unsigned t = __shfl_down_sync(0xffffffffu, inc, off);
            if (lane + off < 32) inc += t;
        }
        const unsigned above = inc - s;
        unsigned dfound = 0u, kfound = 0u;
        bool found = false;
#pragma unroll
        for (int r = 7; r >= 0; r--) {
            unsigned cge  = above + loc[r];
            unsigned cge1 = above + (r < 7 ? loc[r + 1] : 0u);
            if (cge >= k && cge1 < k) {
                dfound = (unsigned)(lane * 8 + r);
                kfound = k - cge1;
                found = true;
            }
        }
        unsigned bal = __ballot_sync(0xffffffffu, found);
        int src = __ffs(bal) - 1;
        dfound = __shfl_sync(0xffffffffu, dfound, src);
        kfound = __shfl_sync(0xffffffffu, kfound, src);
        k = kfound;
        prefix |= dfound << shift;
        mask   |= 0xFFu << shift;
        __syncwarp();
    }
    const float thrv = __uint_as_float(prefix);

#pragma unroll
    for (int i = 0; i < 8; i++) {
        int n = i * 128 + lane * 4;
        float4 vv = *(const float4*)(&v[w][n]);
        float res[4];
        const float* vp = &vv.x;
#pragma unroll
        for (int jc = 0; jc < 4; jc++) {
            float val = vp[jc];
            float av = fabsf(val);
            float th = theta * (1.0f / (xabs[i * 4 + jc] / 0.1f + 1.0f));
            float st = copysignf(fmaxf(av - th, 0.0f), val);
            res[jc] = (av > thrv) ? val : st;
        }
        if (LAST) {
            *(float4*)(outp + base + n) =
                make_float4(res[0], res[1], res[2], res[3]);
        } else {
            uint2 ho, lo2;
            h2split(make_float2(res[0], res[1]), ho.x, lo2.x);
            h2split(make_float2(res[2], res[3]), ho.y, lo2.y);
            *(uint2*)(xh2 + base2 + (n >> 1)) = ho;
            *(uint2*)(xl2 + base2 + (n >> 1)) = lo2;
        }
    }
}

// ---------------------------------------------------------------------------
// Prep / misc kernels
// ---------------------------------------------------------------------------
__global__ void split_h2_kernel(const float* __restrict__ in,
                                uint32_t* __restrict__ hi2,
                                uint32_t* __restrict__ lo2, size_t npairs,
                                float scale)
{
    size_t i = (size_t)blockIdx.x * blockDim.x + threadIdx.x;
    if (i < npairs) {
        float2 vq = ((const float2*)in)[i];
        vq.x *= scale;
        vq.y *= scale;
        uint32_t h, l;
        h2split(vq, h, l);
        hi2[i] = h;
        lo2[i] = l;
    }
}

__global__ void transpose_w_kernel(const float* __restrict__ Win,
                                   float* __restrict__ wt)
{
    __shared__ float tile[32][33];
    int n0 = blockIdx.x * 32;
    int m0 = blockIdx.y * 32;
    int tx = threadIdx.x, ty = threadIdx.y;
    for (int i = ty; i < 32; i += 8)
        tile[i][tx] = Win[(size_t)(m0 + i) * Ndim + n0 + tx];
    __syncthreads();
    for (int i = ty; i < 32; i += 8)
        wt[(size_t)(n0 + i) * Mdim + m0 + tx] = tile[tx][i];
}

__global__ void zero_kernel(float* __restrict__ p, size_t n)
{
    for (size_t i = (size_t)blockIdx.x * blockDim.x + threadIdx.x; i < n;
         i += (size_t)gridDim.x * blockDim.x)
        p[i] = 0.0f;
}

// ---------------------------------------------------------------------------
// Launch
// ---------------------------------------------------------------------------
extern "C" void kernel_launch(void* const* d_in, const int* in_sizes, int n_in,
                              void* d_out, int out_size)
{
    const float* y     = (const float*)d_in[0];
    const float* phi   = (const float*)d_in[1];
    const float* W     = (const float*)d_in[2];
    const float* gamma = (const float*)d_in[3];
    const float* theta = (const float*)d_in[4];
    float* out = (float*)d_out;

    float* cp;
    uint32_t *xh2, *xl2, *rh2, *rl2, *phih2, *phil2, *wth2, *wtl2;
    cudaGetSymbolAddress((void**)&cp,    g_c);
    cudaGetSymbolAddress((void**)&xh2,   g_xh2);
    cudaGetSymbolAddress((void**)&xl2,   g_xl2);
    cudaGetSymbolAddress((void**)&rh2,   g_rh2);
    cudaGetSymbolAddress((void**)&rl2,   g_rl2);
    cudaGetSymbolAddress((void**)&phih2, g_phih2);
    cudaGetSymbolAddress((void**)&phil2, g_phil2);
    cudaGetSymbolAddress((void**)&wth2,  g_wth2);
    cudaGetSymbolAddress((void**)&wtl2,  g_wtl2);

    cudaFuncSetAttribute(gemm_tc<1>, cudaFuncAttributeMaxDynamicSharedMemorySize,
                         GEMM_SMEM);
    cudaFuncSetAttribute(gemm_tc<0>, cudaFuncAttributeMaxDynamicSharedMemorySize,
                         GEMM_SMEM);

    // prep: phi packed split; W^T via fp32 transpose into g_c head, split;
    // r(it0) = -y packed split; x = 0.
    split_h2_kernel<<<(Mdim * Ndim / 2 + 255) / 256, 256>>>(
        phi, phih2, phil2, (size_t)Mdim * Ndim / 2, 1.0f);
    transpose_w_kernel<<<dim3(Ndim / 32, Mdim / 32), dim3(32, 8)>>>(W, cp);
    split_h2_kernel<<<(Ndim * Mdim / 2 + 255) / 256, 256>>>(
        cp, wth2, wtl2, (size_t)Ndim * Mdim / 2, 1.0f);
    zero_kernel<<<1024, 256>>>((float*)xh2, (size_t)Bdim * Ndim / 2);
    zero_kernel<<<1024, 256>>>((float*)xl2, (size_t)Bdim * Ndim / 2);

    for (int it = 0; it < Kiter; it++) {
        // r = x @ phi^T - y  (it 0: x = 0 -> r = split(-y))
        if (it == 0) {
            split_h2_kernel<<<(Bdim * Mdim / 2 + 255) / 256, 256>>>(
                y, rh2, rl2, (size_t)Bdim * Mdim / 2, -1.0f);
        } else {
            gemm_tc<1><<<dim3(Mdim / 128, Bdim / 128), 256, GEMM_SMEM>>>(
                xh2, xl2, phih2, phil2, nullptr, rh2, rl2, y, Ndim, Mdim);
        }
        // c = r @ W  (fp32 out)
        gemm_tc<0><<<dim3(Ndim / 128, Bdim / 128), 256, GEMM_SMEM>>>(
            rh2, rl2, wth2, wtl2, cp, nullptr, nullptr, nullptr, Mdim, Ndim);
        // x = soft_threshold(x - gamma*c, theta*g(|x|), 50)
        if (it == Kiter - 1)
            update_kernel<1><<<Bdim / 8, 256>>>(xh2, xl2, cp, out,
                                                gamma, theta, it);
        else
            update_kernel<0><<<Bdim / 8, 256>>>(xh2, xl2, cp, nullptr,
                                                gamma, theta, it);
    }

    // zero the tail (the two (K,1) zero outputs appended after x)
    long long tail = (long long)out_size - (long long)Ndim * Bdim;
    if (tail > 0)
        zero_kernel<<<1, 256>>>(out + (size_t)Ndim * Bdim, (size_t)tail);
}